// round 10
// baseline (speedup 1.0000x reference)
#include <cuda_runtime.h>
#include <cuda_fp16.h>
#include <math.h>
#include <stdint.h>

// Problem constants
#define B_  64
#define T_  1024
#define C_  256
#define BR  64               // query rows per CTA (= key tile)
#define NTILE (T_ / BR)      // 16
#define OSS 260              // final O staging stride (floats)

// SMEM byte offsets (per CTA ~109 KB -> 2 CTAs/SM)
#define OF_Q   0             // 64 rows x 528B
#define OF_X0  33792         // 64 rows x 528B (double-buffered K=V tile)
#define OF_X1  67584
#define OF_P   101376        // 64 rows x 144B fp16 P (odd-granule stride)
#define OF_AS  110592        // alpha[64]
#define OF_LS  110848        // l[64]
#define OF_MU  111104        // mu[64]
#define OF_RS  111360        // rstd[64]
#define SMEM_TOTAL 111616

// Device scratch
__device__ __half g_xh[B_ * T_ * C_];
__device__ float  g_cs16[B_ * 16 * C_];
__device__ float  g_colsum[B_ * C_];
__device__ float  g_part[B_ * NTILE * C_];

// ---------------------------------------------------------------------------
static __device__ __forceinline__ uint32_t smem_u32(const void* p) {
    return (uint32_t)__cvta_generic_to_shared(p);
}
static __device__ __forceinline__ void cp16(uint32_t dst, const void* src) {
    asm volatile("cp.async.cg.shared.global [%0], [%1], 16;" :: "r"(dst), "l"(src));
}
static __device__ __forceinline__ void ldsm4(
    uint32_t& r0, uint32_t& r1, uint32_t& r2, uint32_t& r3, uint32_t a)
{
    asm volatile("ldmatrix.sync.aligned.m8n8.x4.shared.b16 {%0,%1,%2,%3}, [%4];"
                 : "=r"(r0), "=r"(r1), "=r"(r2), "=r"(r3) : "r"(a));
}
static __device__ __forceinline__ void ldsm4t(
    uint32_t& r0, uint32_t& r1, uint32_t& r2, uint32_t& r3, uint32_t a)
{
    asm volatile("ldmatrix.sync.aligned.m8n8.x4.trans.shared.b16 {%0,%1,%2,%3}, [%4];"
                 : "=r"(r0), "=r"(r1), "=r"(r2), "=r"(r3) : "r"(a));
}
static __device__ __forceinline__ void mma_f16(
    float* d, uint32_t a0, uint32_t a1, uint32_t a2, uint32_t a3,
    uint32_t b0, uint32_t b1)
{
    asm volatile(
        "mma.sync.aligned.m16n8k16.row.col.f32.f16.f16.f32 "
        "{%0,%1,%2,%3},{%4,%5,%6,%7},{%8,%9},{%0,%1,%2,%3};"
        : "+f"(d[0]), "+f"(d[1]), "+f"(d[2]), "+f"(d[3])
        : "r"(a0), "r"(a1), "r"(a2), "r"(a3), "r"(b0), "r"(b1));
}
static __device__ __forceinline__ uint32_t packh2(float x, float y) {
    __half2 h = __floats2half2_rn(x, y);
    return *(uint32_t*)&h;
}

// ---------------------------------------------------------------------------
// Kernel 1: fp16 copy of x + exact fp32 colsum partials
// ---------------------------------------------------------------------------
__global__ void prep_kernel(const float* __restrict__ x) {
    const int b = blockIdx.x, ch = blockIdx.y, c = threadIdx.x;
    const size_t base = ((size_t)b * T_ + (size_t)ch * 64) * C_ + c;
    const float* xp = x + base;
    __half* op = g_xh + base;
    float s = 0.f;
#pragma unroll 8
    for (int t = 0; t < 64; t++) {
        float v = xp[(size_t)t * C_];
        s += v;
        op[(size_t)t * C_] = __float2half_rn(v);
    }
    g_cs16[(b * 16 + ch) * C_ + c] = s;
}

__global__ void colsum_reduce_kernel() {
    const int b = blockIdx.x, c = threadIdx.x;
    float s = 0.f;
#pragma unroll
    for (int i = 0; i < 16; i++) s += g_cs16[(b * 16 + i) * C_ + c];
    g_colsum[b * C_ + c] = s;
}

// ---------------------------------------------------------------------------
// Kernel 2: flash attention.  Stage A: warp = 16 q-rows x 64 keys, softmax
// in registers.  P+alpha through smem once.  Stage B: warp = 64 rows x its
// 64-col slice (minimal trans-ldsm).  128 thr, 2 CTAs/SM.
// ---------------------------------------------------------------------------
__global__ void __launch_bounds__(128, 2)
attn_kernel(const int* __restrict__ km, const float* __restrict__ gamma,
            const float* __restrict__ beta)
{
    extern __shared__ char smc[];
    float* smf = (float*)smc;
    const uint32_t sb = smem_u32(smc);

    const int qt   = 15 - blockIdx.x;        // heavy tiles first
    const int b    = blockIdx.y;
    const int tid  = threadIdx.x;
    const int lane = tid & 31;
    const int w    = tid >> 5;
    const int jj   = lane & 3;
    const int g8   = lane >> 2;
    const int l15  = lane & 15;
    const int lh   = lane >> 4;
    const int q0   = qt * BR;
    const int r0   = w * 16 + g8;            // stage-A row (second: +8)
    const int grow0 = q0 + r0, grow1 = grow0 + 8;
    const __half* xb = g_xh + (size_t)b * T_ * C_;

    const uint32_t aQ = sb + OF_Q + (uint32_t)(w * 16 + l15) * 528 + lh * 16;

    // Prefetch Q + X tile 0
#pragma unroll
    for (int it = 0; it < 16; it++) {
        int idx = tid + it * 128;
        int r = idx >> 5, g = idx & 31;
        cp16(sb + OF_Q + r * 528 + g * 16, xb + (size_t)(q0 + r) * C_ + g * 8);
    }
#pragma unroll
    for (int it = 0; it < 16; it++) {
        int idx = tid + it * 128;
        int r = idx >> 5, g = idx & 31;
        cp16(sb + OF_X0 + r * 528 + g * 16, xb + (size_t)r * C_ + g * 8);
    }
    asm volatile("cp.async.commit_group;");

    float Oacc[32][4];                        // stage-B layout: [rb*8+cb*2+h][e]
#pragma unroll
    for (int i = 0; i < 32; i++)
#pragma unroll
        for (int e = 0; e < 4; e++) Oacc[i][e] = 0.f;
    float m0 = -INFINITY, m1 = -INFINITY, l0 = 0.f, l1 = 0.f;

    for (int st = 0; st <= qt; st++) {
        const uint32_t Xoff = (st & 1) ? OF_X1 : OF_X0;
        const int s0 = st * BR;

        asm volatile("cp.async.wait_group 0;");
        __syncthreads();                      // X[st] ready; P/alpha/X[other] free

        if (st < qt) {                        // prefetch next tile
            const uint32_t Xn = ((st + 1) & 1) ? OF_X1 : OF_X0;
            const __half* src = xb + (size_t)(st + 1) * BR * C_;
#pragma unroll
            for (int it = 0; it < 16; it++) {
                int idx = tid + it * 128;
                int r = idx >> 5, g = idx & 31;
                cp16(sb + Xn + r * 528 + g * 16, src + (size_t)r * C_ + g * 8);
            }
            asm volatile("cp.async.commit_group;");
        }

        // key-padding mask pairs for my 16 columns
        int2 kmv[8];
#pragma unroll
        for (int nt = 0; nt < 8; nt++)
            kmv[nt] = *(const int2*)(km + b * T_ + s0 + nt * 8 + 2 * jj);

        // ---- Stage A: S = Q K^T, warp tile 16x64 ----
        uint32_t aK[4];
#pragma unroll
        for (int nb = 0; nb < 4; nb++)
            aK[nb] = sb + Xoff + (uint32_t)(nb * 16 + (lane & 7) + lh * 8) * 528
                     + ((lane >> 3) & 1) * 16;

        float sacc[8][4];
#pragma unroll
        for (int nt = 0; nt < 8; nt++)
#pragma unroll
            for (int e = 0; e < 4; e++) sacc[nt][e] = 0.f;

#pragma unroll
        for (int k = 0; k < 16; k++) {
            uint32_t a0, a1, a2, a3;
            ldsm4(a0, a1, a2, a3, aQ + k * 32);
#pragma unroll
            for (int nb = 0; nb < 4; nb++) {
                uint32_t b0, b1, b2, b3;
                ldsm4(b0, b1, b2, b3, aK[nb] + k * 32);
                mma_f16(sacc[2 * nb],     a0, a1, a2, a3, b0, b1);
                mma_f16(sacc[2 * nb + 1], a0, a1, a2, a3, b2, b3);
            }
        }

        // ---- Mask + in-register online softmax (quad shuffles) ----
#pragma unroll
        for (int nt = 0; nt < 8; nt++) {
#pragma unroll
            for (int e = 0; e < 2; e++) {
                int key = s0 + nt * 8 + 2 * jj + e;
                int ok = e ? kmv[nt].y : kmv[nt].x;
                sacc[nt][e]     = ((key <= grow0) && ok) ? sacc[nt][e] * 0.0625f     : -INFINITY;
                sacc[nt][2 + e] = ((key <= grow1) && ok) ? sacc[nt][2 + e] * 0.0625f : -INFINITY;
            }
        }
        float mt0 = -INFINITY, mt1 = -INFINITY;
#pragma unroll
        for (int nt = 0; nt < 8; nt++) {
            mt0 = fmaxf(mt0, fmaxf(sacc[nt][0], sacc[nt][1]));
            mt1 = fmaxf(mt1, fmaxf(sacc[nt][2], sacc[nt][3]));
        }
        mt0 = fmaxf(mt0, __shfl_xor_sync(0xffffffffu, mt0, 1));
        mt0 = fmaxf(mt0, __shfl_xor_sync(0xffffffffu, mt0, 2));
        mt1 = fmaxf(mt1, __shfl_xor_sync(0xffffffffu, mt1, 1));
        mt1 = fmaxf(mt1, __shfl_xor_sync(0xffffffffu, mt1, 2));
        const float mn0 = fmaxf(m0, mt0), mn1 = fmaxf(m1, mt1);
        const float al0 = (m0 == -INFINITY) ? 0.f : __expf(m0 - mn0);
        const float al1 = (m1 == -INFINITY) ? 0.f : __expf(m1 - mn1);

        float sum0 = 0.f, sum1 = 0.f;
        uint32_t ph0[8], ph1[8];
#pragma unroll
        for (int nt = 0; nt < 8; nt++) {
            float a = sacc[nt][0], bq = sacc[nt][1];
            float c = sacc[nt][2], d = sacc[nt][3];
            float pa = (a  == -INFINITY) ? 0.f : __expf(a  - mn0);
            float pb = (bq == -INFINITY) ? 0.f : __expf(bq - mn0);
            float pc = (c  == -INFINITY) ? 0.f : __expf(c  - mn1);
            float pd = (d  == -INFINITY) ? 0.f : __expf(d  - mn1);
            sum0 += pa + pb;  sum1 += pc + pd;
            ph0[nt] = packh2(pa, pb);
            ph1[nt] = packh2(pc, pd);
        }
        sum0 += __shfl_xor_sync(0xffffffffu, sum0, 1);
        sum0 += __shfl_xor_sync(0xffffffffu, sum0, 2);
        sum1 += __shfl_xor_sync(0xffffffffu, sum1, 1);
        sum1 += __shfl_xor_sync(0xffffffffu, sum1, 2);
        l0 = l0 * al0 + sum0;  m0 = mn0;
        l1 = l1 * al1 + sum1;  m1 = mn1;

        // ---- P + alpha -> smem ----
#pragma unroll
        for (int nt = 0; nt < 8; nt++) {
            uint32_t cbyte = (uint32_t)(nt * 8 + 2 * jj) * 2;
            *(uint32_t*)(smc + OF_P + r0 * 144 + cbyte)       = ph0[nt];
            *(uint32_t*)(smc + OF_P + (r0 + 8) * 144 + cbyte) = ph1[nt];
        }
        if (jj == 0) {
            smf[OF_AS / 4 + r0]     = al0;
            smf[OF_AS / 4 + r0 + 8] = al1;
        }
        __syncthreads();                      // P + alpha visible

        // ---- Stage B: warp w computes all 64 rows x cols [64w, 64w+64) ----
        {
            float al[4][2];
#pragma unroll
            for (int rb = 0; rb < 4; rb++) {
                al[rb][0] = smf[OF_AS / 4 + rb * 16 + g8];
                al[rb][1] = smf[OF_AS / 4 + rb * 16 + g8 + 8];
            }
#pragma unroll
            for (int i = 0; i < 32; i++) {
                const int rb = i >> 3;
                Oacc[i][0] *= al[rb][0]; Oacc[i][1] *= al[rb][0];
                Oacc[i][2] *= al[rb][1]; Oacc[i][3] *= al[rb][1];
            }

            uint32_t aPb[4];
#pragma unroll
            for (int rb = 0; rb < 4; rb++)
                aPb[rb] = sb + OF_P + (uint32_t)(rb * 16 + l15) * 144 + lh * 16;
            const uint32_t aXw = sb + Xoff + (uint32_t)l15 * 528
                                 + (uint32_t)w * 128 + lh * 16;

#pragma unroll
            for (int ks = 0; ks < 4; ks++) {
                uint32_t pa[4][4];
#pragma unroll
                for (int rb = 0; rb < 4; rb++)
                    ldsm4(pa[rb][0], pa[rb][1], pa[rb][2], pa[rb][3],
                          aPb[rb] + ks * 32);
#pragma unroll
                for (int cb = 0; cb < 4; cb++) {
                    uint32_t x0, x1, x2, x3;
                    ldsm4t(x0, x1, x2, x3, aXw + ks * 16 * 528 + cb * 32);
#pragma unroll
                    for (int rb = 0; rb < 4; rb++) {
                        mma_f16(Oacc[rb * 8 + cb * 2],
                                pa[rb][0], pa[rb][1], pa[rb][2], pa[rb][3], x0, x1);
                        mma_f16(Oacc[rb * 8 + cb * 2 + 1],
                                pa[rb][0], pa[rb][1], pa[rb][2], pa[rb][3], x2, x3);
                    }
                }
            }
        }
    }

    // ---- publish l, then epilogue ----
    if (jj == 0) {
        smf[OF_LS / 4 + r0]     = l0;
        smf[OF_LS / 4 + r0 + 8] = l1;
    }
    __syncthreads();                           // l visible; all smem reusable

    float* Os = smf;
#pragma unroll
    for (int rb = 0; rb < 4; rb++) {
        const int row0 = rb * 16 + g8, row1 = row0 + 8;
        const float lv0 = smf[OF_LS / 4 + row0], lv1 = smf[OF_LS / 4 + row1];
        const bool d0 = (lv0 == 0.f), d1 = (lv1 == 0.f);
        const float inv0 = d0 ? 0.f : (1.f / lv0);
        const float inv1 = d1 ? 0.f : (1.f / lv1);
#pragma unroll
        for (int cb = 0; cb < 4; cb++)
#pragma unroll
            for (int h = 0; h < 2; h++)
#pragma unroll
                for (int e = 0; e < 2; e++) {
                    const int c = w * 64 + cb * 16 + h * 8 + 2 * jj + e;
                    const float cm = g_colsum[b * C_ + c] * (1.f / 1024.f);
                    const int oi = rb * 8 + cb * 2 + h;
                    Os[row0 * OSS + c] = d0 ? cm : Oacc[oi][e]     * inv0;
                    Os[row1 * OSS + c] = d1 ? cm : Oacc[oi][2 + e] * inv1;
                }
    }
    __syncthreads();

    // ---- LayerNorm stats (2 threads per row) ----
    {
        const int r = tid >> 1, hf = tid & 1;
        const float* row = Os + r * OSS + hf * 128;
        float s1 = 0.f;
#pragma unroll 8
        for (int c = 0; c < 128; c++) s1 += row[c];
        s1 += __shfl_xor_sync(0xffffffffu, s1, 1);
        const float mu = s1 * (1.f / 256.f);
        float s2 = 0.f;
#pragma unroll 8
        for (int c = 0; c < 128; c++) { float d = row[c] - mu; s2 += d * d; }
        s2 += __shfl_xor_sync(0xffffffffu, s2, 1);
        const float rstd = rsqrtf(s2 * (1.f / 256.f) + 1e-9f);
        if (hf == 0) { smf[OF_MU / 4 + r] = mu; smf[OF_RS / 4 + r] = rstd; }
    }
    __syncthreads();

    // ---- Column partials (each thread: cols tid, tid+128) ----
    {
        float acc0 = 0.f, acc1 = 0.f;
#pragma unroll 4
        for (int r = 0; r < BR; r++) {
            const float muv = smf[OF_MU / 4 + r], rsv = smf[OF_RS / 4 + r];
            acc0 += (Os[r * OSS + tid]       - muv) * rsv;
            acc1 += (Os[r * OSS + tid + 128] - muv) * rsv;
        }
        float* gp = g_part + (size_t)(b * NTILE + qt) * C_;
        gp[tid]       = gamma[tid]       * acc0 + 64.f * beta[tid];
        gp[tid + 128] = gamma[tid + 128] * acc1 + 64.f * beta[tid + 128];
    }
}

// ---------------------------------------------------------------------------
// Kernel 3: reduce q-tile partials -> mean over T
// ---------------------------------------------------------------------------
__global__ void finalize_kernel(float* __restrict__ out) {
    const int b = blockIdx.x, c = threadIdx.x;
    float s = 0.f;
#pragma unroll
    for (int qtl = 0; qtl < NTILE; qtl++) s += g_part[(b * NTILE + qtl) * C_ + c];
    out[b * C_ + c] = s * (1.f / 1024.f);
}

// ---------------------------------------------------------------------------
extern "C" void kernel_launch(void* const* d_in, const int* in_sizes, int n_in,
                              void* d_out, int out_size)
{
    const float* x     = (const float*)d_in[0];
    const int*   km    = (const int*)  d_in[1];
    const float* gamma = (const float*)d_in[2];
    const float* beta  = (const float*)d_in[3];
    float*       out   = (float*)d_out;

    cudaFuncSetAttribute(attn_kernel,
                         cudaFuncAttributeMaxDynamicSharedMemorySize, SMEM_TOTAL);

    prep_kernel<<<dim3(B_, 16), 256>>>(x);
    colsum_reduce_kernel<<<B_, 256>>>();
    attn_kernel<<<dim3(NTILE, B_), 128, SMEM_TOTAL>>>(km, gamma, beta);
    finalize_kernel<<<B_, 256>>>(out);
}

// round 11
// speedup vs baseline: 1.0711x; 1.0711x over previous
#include <cuda_runtime.h>
#include <cuda_fp16.h>
#include <math.h>
#include <stdint.h>

// Problem constants
#define B_  64
#define T_  1024
#define C_  256
#define BR  64               // query rows per CTA (= key tile)
#define NTILE (T_ / BR)      // 16
#define OSS 260              // final O staging stride (floats)

// SMEM byte offsets (per CTA ~99.5 KB -> 2 CTAs/SM)
#define OF_Q   0             // 64 rows x 528B
#define OF_X0  33792         // 64 rows x 528B (double-buffered K=V tile)
#define OF_X1  67584
#define OF_MU  101376        // mu[64]
#define OF_RS  101632        // rstd[64]
#define SMEM_TOTAL 101888

// Device scratch
__device__ __half g_xh[B_ * T_ * C_];
__device__ float  g_cs16[B_ * 16 * C_];
__device__ float  g_colsum[B_ * C_];
__device__ float  g_part[B_ * NTILE * C_];

// ---------------------------------------------------------------------------
static __device__ __forceinline__ uint32_t smem_u32(const void* p) {
    return (uint32_t)__cvta_generic_to_shared(p);
}
static __device__ __forceinline__ void cp16(uint32_t dst, const void* src) {
    asm volatile("cp.async.cg.shared.global [%0], [%1], 16;" :: "r"(dst), "l"(src));
}
static __device__ __forceinline__ void ldsm4(
    uint32_t& r0, uint32_t& r1, uint32_t& r2, uint32_t& r3, uint32_t a)
{
    asm volatile("ldmatrix.sync.aligned.m8n8.x4.shared.b16 {%0,%1,%2,%3}, [%4];"
                 : "=r"(r0), "=r"(r1), "=r"(r2), "=r"(r3) : "r"(a));
}
static __device__ __forceinline__ void ldsm4t(
    uint32_t& r0, uint32_t& r1, uint32_t& r2, uint32_t& r3, uint32_t a)
{
    asm volatile("ldmatrix.sync.aligned.m8n8.x4.trans.shared.b16 {%0,%1,%2,%3}, [%4];"
                 : "=r"(r0), "=r"(r1), "=r"(r2), "=r"(r3) : "r"(a));
}
static __device__ __forceinline__ void mma_f16(
    float* d, uint32_t a0, uint32_t a1, uint32_t a2, uint32_t a3,
    uint32_t b0, uint32_t b1)
{
    asm volatile(
        "mma.sync.aligned.m16n8k16.row.col.f32.f16.f16.f32 "
        "{%0,%1,%2,%3},{%4,%5,%6,%7},{%8,%9},{%0,%1,%2,%3};"
        : "+f"(d[0]), "+f"(d[1]), "+f"(d[2]), "+f"(d[3])
        : "r"(a0), "r"(a1), "r"(a2), "r"(a3), "r"(b0), "r"(b1));
}
static __device__ __forceinline__ uint32_t packh2(float x, float y) {
    __half2 h = __floats2half2_rn(x, y);
    return *(uint32_t*)&h;
}

// ---------------------------------------------------------------------------
// Kernel 1: fp16 copy of x + exact fp32 colsum partials
// ---------------------------------------------------------------------------
__global__ void prep_kernel(const float* __restrict__ x) {
    const int b = blockIdx.x, ch = blockIdx.y, c = threadIdx.x;
    const size_t base = ((size_t)b * T_ + (size_t)ch * 64) * C_ + c;
    const float* xp = x + base;
    __half* op = g_xh + base;
    float s = 0.f;
#pragma unroll 8
    for (int t = 0; t < 64; t++) {
        float v = xp[(size_t)t * C_];
        s += v;
        op[(size_t)t * C_] = __float2half_rn(v);
    }
    g_cs16[(b * 16 + ch) * C_ + c] = s;
}

__global__ void colsum_reduce_kernel() {
    const int b = blockIdx.x, c = threadIdx.x;
    float s = 0.f;
#pragma unroll
    for (int i = 0; i < 16; i++) s += g_cs16[(b * 16 + i) * C_ + c];
    g_colsum[b * C_ + c] = s;
}

// ---------------------------------------------------------------------------
// Kernel 2: flash attention, fp16 mma, register-resident P + in-register
// online softmax. Global heavy-first launch (all qt=15 CTAs first).
// Diagonal tiles skip fully-masked MMA blocks. 128 thr, 2 CTAs/SM.
// ---------------------------------------------------------------------------
__global__ void __launch_bounds__(128, 2)
attn_kernel(const int* __restrict__ km, const float* __restrict__ gamma,
            const float* __restrict__ beta)
{
    extern __shared__ char smc[];
    float* smf = (float*)smc;
    const uint32_t sb = smem_u32(smc);

    const int qt   = 15 - blockIdx.y;        // ALL heavy tiles launch first
    const int b    = blockIdx.x;
    const int tid  = threadIdx.x;
    const int lane = tid & 31;
    const int w    = tid >> 5;
    const int jj   = lane & 3;
    const int g8   = lane >> 2;
    const int l15  = lane & 15;
    const int lh   = lane >> 4;
    const int q0   = qt * BR;
    const int row0 = w * 16 + g8;            // local q row (second: +8)
    const int grow0 = q0 + row0, grow1 = grow0 + 8;
    const __half* xb = g_xh + (size_t)b * T_ * C_;

    const uint32_t aQ = sb + OF_Q + (uint32_t)(w * 16 + l15) * 528 + lh * 16;

    // Prefetch Q + X tile 0 (one group)
#pragma unroll
    for (int it = 0; it < 16; it++) {
        int idx = tid + it * 128;
        int r = idx >> 5, g = idx & 31;
        cp16(sb + OF_Q + r * 528 + g * 16, xb + (size_t)(q0 + r) * C_ + g * 8);
    }
#pragma unroll
    for (int it = 0; it < 16; it++) {
        int idx = tid + it * 128;
        int r = idx >> 5, g = idx & 31;
        cp16(sb + OF_X0 + r * 528 + g * 16, xb + (size_t)r * C_ + g * 8);
    }
    asm volatile("cp.async.commit_group;");

    float Oacc[32][4];
#pragma unroll
    for (int i = 0; i < 32; i++)
#pragma unroll
        for (int e = 0; e < 4; e++) Oacc[i][e] = 0.f;
    float m0 = -INFINITY, m1 = -INFINITY, l0 = 0.f, l1 = 0.f;

    for (int st = 0; st <= qt; st++) {
        const uint32_t Xoff = (st & 1) ? OF_X1 : OF_X0;
        const int s0 = st * BR;
        const bool diag = (st == qt);

        asm volatile("cp.async.wait_group 0;");
        __syncthreads();                      // X[st] visible; X[(st+1)&1] free

        if (st < qt) {                        // prefetch next tile
            const uint32_t Xn = ((st + 1) & 1) ? OF_X1 : OF_X0;
            const __half* src = xb + (size_t)(st + 1) * BR * C_;
#pragma unroll
            for (int it = 0; it < 16; it++) {
                int idx = tid + it * 128;
                int r = idx >> 5, g = idx & 31;
                cp16(sb + Xn + r * 528 + g * 16, src + (size_t)r * C_ + g * 8);
            }
            asm volatile("cp.async.commit_group;");
        }

        // key-padding mask pairs for my 16 columns
        int2 kmv[8];
#pragma unroll
        for (int nt = 0; nt < 8; nt++)
            kmv[nt] = *(const int2*)(km + b * T_ + s0 + nt * 8 + 2 * jj);

        // ---- Stage A: S = Q K^T, warp tile 16x64 ----
        // Diagonal tile: key block nb is fully causal-masked when nb > w.
        uint32_t aK[4];
#pragma unroll
        for (int nb = 0; nb < 4; nb++)
            aK[nb] = sb + Xoff + (uint32_t)(nb * 16 + (lane & 7) + lh * 8) * 528
                     + ((lane >> 3) & 1) * 16;
        const int nbmax = diag ? (w + 1) : 4;   // warp-uniform

        float sacc[8][4];
#pragma unroll
        for (int nt = 0; nt < 8; nt++)
#pragma unroll
            for (int e = 0; e < 4; e++) sacc[nt][e] = 0.f;

#pragma unroll
        for (int k = 0; k < 16; k++) {
            uint32_t a0, a1, a2, a3;
            ldsm4(a0, a1, a2, a3, aQ + k * 32);
#pragma unroll
            for (int nb = 0; nb < 4; nb++) {
                if (nb < nbmax) {
                    uint32_t b0, b1, b2, b3;
                    ldsm4(b0, b1, b2, b3, aK[nb] + k * 32);
                    mma_f16(sacc[2 * nb],     a0, a1, a2, a3, b0, b1);
                    mma_f16(sacc[2 * nb + 1], a0, a1, a2, a3, b2, b3);
                }
            }
        }

        // ---- Mask + in-register online softmax (quad shuffles only) ----
#pragma unroll
        for (int nt = 0; nt < 8; nt++) {
#pragma unroll
            for (int e = 0; e < 2; e++) {
                int key = s0 + nt * 8 + 2 * jj + e;
                int ok = e ? kmv[nt].y : kmv[nt].x;
                sacc[nt][e]     = ((key <= grow0) && ok) ? sacc[nt][e] * 0.0625f     : -INFINITY;
                sacc[nt][2 + e] = ((key <= grow1) && ok) ? sacc[nt][2 + e] * 0.0625f : -INFINITY;
            }
        }
        float mt0 = -INFINITY, mt1 = -INFINITY;
#pragma unroll
        for (int nt = 0; nt < 8; nt++) {
            mt0 = fmaxf(mt0, fmaxf(sacc[nt][0], sacc[nt][1]));
            mt1 = fmaxf(mt1, fmaxf(sacc[nt][2], sacc[nt][3]));
        }
        mt0 = fmaxf(mt0, __shfl_xor_sync(0xffffffffu, mt0, 1));
        mt0 = fmaxf(mt0, __shfl_xor_sync(0xffffffffu, mt0, 2));
        mt1 = fmaxf(mt1, __shfl_xor_sync(0xffffffffu, mt1, 1));
        mt1 = fmaxf(mt1, __shfl_xor_sync(0xffffffffu, mt1, 2));
        const float mn0 = fmaxf(m0, mt0), mn1 = fmaxf(m1, mt1);
        const float al0 = (m0 == -INFINITY) ? 0.f : __expf(m0 - mn0);
        const float al1 = (m1 == -INFINITY) ? 0.f : __expf(m1 - mn1);

        float p0[8][2], p1[8][2], sum0 = 0.f, sum1 = 0.f;
#pragma unroll
        for (int nt = 0; nt < 8; nt++) {
#pragma unroll
            for (int e = 0; e < 2; e++) {
                float a = sacc[nt][e],     pa = (a == -INFINITY) ? 0.f : __expf(a - mn0);
                float c = sacc[nt][2 + e], pc = (c == -INFINITY) ? 0.f : __expf(c - mn1);
                p0[nt][e] = pa; sum0 += pa;
                p1[nt][e] = pc; sum1 += pc;
            }
        }
        sum0 += __shfl_xor_sync(0xffffffffu, sum0, 1);
        sum0 += __shfl_xor_sync(0xffffffffu, sum0, 2);
        sum1 += __shfl_xor_sync(0xffffffffu, sum1, 1);
        sum1 += __shfl_xor_sync(0xffffffffu, sum1, 2);
        l0 = l0 * al0 + sum0;  m0 = mn0;
        l1 = l1 * al1 + sum1;  m1 = mn1;

        // rescale O accumulators
#pragma unroll
        for (int i = 0; i < 32; i++) {
            Oacc[i][0] *= al0; Oacc[i][1] *= al0;
            Oacc[i][2] *= al1; Oacc[i][3] *= al1;
        }

        // pack P into A-fragments (C-frag layout == A-frag layout)
        uint32_t pA[4][4];
#pragma unroll
        for (int kb = 0; kb < 4; kb++) {
            pA[kb][0] = packh2(p0[2 * kb][0],     p0[2 * kb][1]);
            pA[kb][1] = packh2(p1[2 * kb][0],     p1[2 * kb][1]);
            pA[kb][2] = packh2(p0[2 * kb + 1][0], p0[2 * kb + 1][1]);
            pA[kb][3] = packh2(p1[2 * kb + 1][0], p1[2 * kb + 1][1]);
        }

        // ---- Stage B: O += P @ X, warp tile 16x256 ----
        // Diagonal tile: key chunk ks has P identically 0 when ks > w.
        const uint32_t aXb = sb + Xoff + (uint32_t)l15 * 528 + lh * 16;
        const int ksmax = diag ? (w + 1) : 4;   // warp-uniform
#pragma unroll
        for (int ks = 0; ks < 4; ks++) {
            if (ks < ksmax) {
#pragma unroll
                for (int n16 = 0; n16 < 16; n16++) {
                    uint32_t x0, x1, x2, x3;
                    ldsm4t(x0, x1, x2, x3, aXb + ks * 16 * 528 + n16 * 32);
                    mma_f16(Oacc[2 * n16],     pA[ks][0], pA[ks][1], pA[ks][2], pA[ks][3], x0, x1);
                    mma_f16(Oacc[2 * n16 + 1], pA[ks][0], pA[ks][1], pA[ks][2], pA[ks][3], x2, x3);
                }
            }
        }
    }

    // ---- Epilogue: normalize / degenerate fixup -> Os staging ----
    __syncthreads();                           // all compute done; reuse Q/X0 smem
    float* Os = smf;
    {
        const bool d0 = (l0 == 0.f), d1 = (l1 == 0.f);
        const float inv0 = d0 ? 0.f : (1.f / l0);
        const float inv1 = d1 ? 0.f : (1.f / l1);
#pragma unroll
        for (int nt2 = 0; nt2 < 32; nt2++)
#pragma unroll
            for (int e = 0; e < 2; e++) {
                const int c = nt2 * 8 + 2 * jj + e;
                const float cm = g_colsum[b * C_ + c] * (1.f / 1024.f);
                Os[row0 * OSS + c]       = d0 ? cm : Oacc[nt2][e] * inv0;
                Os[(row0 + 8) * OSS + c] = d1 ? cm : Oacc[nt2][2 + e] * inv1;
            }
    }
    __syncthreads();

    // ---- LayerNorm stats (2 threads per row) ----
    {
        const int r = tid >> 1, hf = tid & 1;
        const float* row = Os + r * OSS + hf * 128;
        float s1 = 0.f;
#pragma unroll 8
        for (int c = 0; c < 128; c++) s1 += row[c];
        s1 += __shfl_xor_sync(0xffffffffu, s1, 1);
        const float mu = s1 * (1.f / 256.f);
        float s2 = 0.f;
#pragma unroll 8
        for (int c = 0; c < 128; c++) { float d = row[c] - mu; s2 += d * d; }
        s2 += __shfl_xor_sync(0xffffffffu, s2, 1);
        const float rstd = rsqrtf(s2 * (1.f / 256.f) + 1e-9f);
        if (hf == 0) { smf[OF_MU / 4 + r] = mu; smf[OF_RS / 4 + r] = rstd; }
    }
    __syncthreads();

    // ---- Column partials (each thread: cols tid, tid+128) ----
    {
        float acc0 = 0.f, acc1 = 0.f;
#pragma unroll 4
        for (int r = 0; r < BR; r++) {
            const float muv = smf[OF_MU / 4 + r], rsv = smf[OF_RS / 4 + r];
            acc0 += (Os[r * OSS + tid]       - muv) * rsv;
            acc1 += (Os[r * OSS + tid + 128] - muv) * rsv;
        }
        float* gp = g_part + (size_t)(b * NTILE + qt) * C_;
        gp[tid]       = gamma[tid]       * acc0 + 64.f * beta[tid];
        gp[tid + 128] = gamma[tid + 128] * acc1 + 64.f * beta[tid + 128];
    }
}

// ---------------------------------------------------------------------------
// Kernel 3: reduce q-tile partials -> mean over T
// ---------------------------------------------------------------------------
__global__ void finalize_kernel(float* __restrict__ out) {
    const int b = blockIdx.x, c = threadIdx.x;
    float s = 0.f;
#pragma unroll
    for (int qtl = 0; qtl < NTILE; qtl++) s += g_part[(b * NTILE + qtl) * C_ + c];
    out[b * C_ + c] = s * (1.f / 1024.f);
}

// ---------------------------------------------------------------------------
extern "C" void kernel_launch(void* const* d_in, const int* in_sizes, int n_in,
                              void* d_out, int out_size)
{
    const float* x     = (const float*)d_in[0];
    const int*   km    = (const int*)  d_in[1];
    const float* gamma = (const float*)d_in[2];
    const float* beta  = (const float*)d_in[3];
    float*       out   = (float*)d_out;

    cudaFuncSetAttribute(attn_kernel,
                         cudaFuncAttributeMaxDynamicSharedMemorySize, SMEM_TOTAL);

    prep_kernel<<<dim3(B_, 16), 256>>>(x);
    colsum_reduce_kernel<<<B_, 256>>>();
    attn_kernel<<<dim3(B_, NTILE), 128, SMEM_TOTAL>>>(km, gamma, beta);
    finalize_kernel<<<B_, 256>>>(out);
}